// round 10
// baseline (speedup 1.0000x reference)
#include <cuda_runtime.h>
#include <cstdint>
#include <cstddef>

#define DEV_INLINE __device__ __forceinline__

constexpr int D        = 512;       // feature dim
constexpr int FV       = 12;        // video frames
constexpr int THREADS  = 256;       // 8 warps
constexpr int RPW      = 5;         // text rows per warp (single pass)
constexpr int ROWS_CTA = 8 * RPW;   // 40 rows per item
constexpr int GRID     = 296;       // 2 CTAs x 148 SMs, all co-resident

// scratch (allocation-free: __device__ globals)
__device__ float g_part_min[4096];
__device__ float g_part_max[4096];
__device__ unsigned int g_ticket = 0;
__device__ unsigned int g_arrive = 0;
__device__ unsigned int g_exit   = 0;

DEV_INLINE unsigned long long ffma2(unsigned long long a, unsigned long long b,
                                    unsigned long long c) {
    unsigned long long d;
    asm("fma.rn.f32x2 %0, %1, %2, %3;" : "=l"(d) : "l"(a), "l"(b), "l"(c));
    return d;
}

DEV_INLINE float hsum2(unsigned long long v) {
    float lo, hi;
    asm("mov.b64 {%0, %1}, %2;" : "=f"(lo), "=f"(hi) : "l"(v));
    return lo + hi;
}

DEV_INLINE void cp_async16(uint32_t smem_addr, const void* gptr) {
    asm volatile("cp.async.cg.shared.global [%0], [%1], 16;"
                 :: "r"(smem_addr), "l"(gptr));
}
#define CP_COMMIT()  asm volatile("cp.async.commit_group;")
#define CP_WAIT0()   asm volatile("cp.async.wait_group 0;" ::: "memory")

// ---------------------------------------------------------------------------
// Single persistent kernel, cross-item software pipeline.
// Iteration k (steady state):
//   fetch ticket k+1  ->  wait video(k)  ->  issue video(k+1) into other buf
//   -> norms(k) -> mainloop(k) [text via LDG + 1-step prefetch]
//   -> prime item k+1 step-0 text loads (hidden under the tail's shuffles)
//   -> tail(k) -> store partials.
// Video staging, ticket latency and first text step are all covered by
// adjacent compute. Phase 2: grid spin-barrier (all 296 CTAs resident),
// redundant reduce of the L2-resident partials, cooperative output fill.
// Counters reset by last CTA -> graph-replay deterministic (min/max is
// order-independent).
// ---------------------------------------------------------------------------
__global__ void __launch_bounds__(THREADS, 2)
distance_persistent_kernel(const float* __restrict__ text,
                           const float* __restrict__ video,
                           float* __restrict__ out,
                           int T, int B, int chunks)
{
    __shared__ float sv[2][FV * D];       // 2 x 24 KB video tiles
    __shared__ float s_vinv[FV];
    __shared__ float s_wmin[8], s_wmax[8];
    __shared__ float red_mn[THREADS], red_mx[THREADS];
    __shared__ unsigned int s_item, s_next;

    const int tid  = threadIdx.x;
    const int warp = tid >> 5;
    const int lane = tid & 31;
    const int fg   = lane >> 3;    // 0..3 : which group of 3 video rows
    const int dl   = lane & 7;     // 0..7 : which slice of D
    const int n_items = B * chunks;

    // ---------------- prologue: first ticket + first staging ----------------
    if (tid == 0) s_item = atomicAdd(&g_ticket, 1u);
    __syncthreads();
    unsigned int item = s_item;
    bool valid = item < (unsigned int)n_items;
    int cur = 0;

    const float* trp[RPW];
    ulonglong2 tv[RPW];

    if (valid) {
        const int b     = item / chunks;
        const int chunk = item % chunks;
        const char* vsrc = reinterpret_cast<const char*>(video + (size_t)b * FV * D);
        uint32_t svb = (uint32_t)__cvta_generic_to_shared(&sv[0][0]);
        #pragma unroll
        for (int i = tid; i < FV * (D / 4); i += THREADS)
            cp_async16(svb + i * 16, vsrc + i * 16);
        CP_COMMIT();

        const float* tb = text + (size_t)b * (size_t)T * D;
        const int base  = chunk * ROWS_CTA;
        #pragma unroll
        for (int r = 0; r < RPW; r++) {
            int tt = base + warp * RPW + r; if (tt > T - 1) tt = T - 1;
            trp[r] = tb + (size_t)tt * D;
        }
        #pragma unroll
        for (int r = 0; r < RPW; r++)
            tv[r] = *reinterpret_cast<const ulonglong2*>(trp[r] + dl * 4);
    }

    // ---------------- item loop ----------------
    while (valid) {
        if (tid == 0) s_next = atomicAdd(&g_ticket, 1u);
        CP_WAIT0();                       // video(item) resident
        __syncthreads();                  // broadcast s_next; all past prev reads
        const unsigned int next = s_next;
        const bool nvalid = next < (unsigned int)n_items;

        // ---- issue video staging for item k+1 (overlaps all of compute(k)) ----
        if (nvalid) {
            const int nb = next / chunks;
            const char* nvsrc = reinterpret_cast<const char*>(video + (size_t)nb * FV * D);
            uint32_t svb = (uint32_t)__cvta_generic_to_shared(&sv[cur ^ 1][0]);
            #pragma unroll
            for (int i = tid; i < FV * (D / 4); i += THREADS)
                cp_async16(svb + i * 16, nvsrc + i * 16);
            CP_COMMIT();
        }

        // ---- inverse norms of the 12 video rows (from sv[cur]) ----
        const float* svc = &sv[cur][0];
        for (int f = warp; f < FV; f += 8) {
            float s = 0.f;
            #pragma unroll
            for (int c = lane; c < D / 4; c += 32) {
                float4 x = *reinterpret_cast<const float4*>(&svc[f * D + c * 4]);
                s += x.x * x.x + x.y * x.y + x.z * x.z + x.w * x.w;
            }
            #pragma unroll
            for (int o = 16; o > 0; o >>= 1) s += __shfl_xor_sync(0xffffffffu, s, o);
            if (lane == 0) s_vinv[f] = rsqrtf(s);
        }
        __syncthreads();

        const int f0 = fg * 3;
        const float vinv0 = s_vinv[f0 + 0];
        const float vinv1 = s_vinv[f0 + 1];
        const float vinv2 = s_vinv[f0 + 2];
        const float* svp0 = &svc[(f0 + 0) * D];
        const float* svp1 = &svc[(f0 + 1) * D];
        const float* svp2 = &svc[(f0 + 2) * D];

        unsigned long long acc[RPW][3];
        unsigned long long nrm[RPW];
        #pragma unroll
        for (int r = 0; r < RPW; r++) {
            acc[r][0] = 0ull; acc[r][1] = 0ull; acc[r][2] = 0ull; nrm[r] = 0ull;
        }

        // ---- mainloop: video from shared, text from global (1-step prefetch) ----
        #pragma unroll
        for (int s = 0; s < 16; s++) {
            const int off = (dl + 8 * s) * 4;
            ulonglong2 tnx[RPW];
            if (s < 15) {
                const int noff = (dl + 8 * (s + 1)) * 4;
                #pragma unroll
                for (int r = 0; r < RPW; r++)
                    tnx[r] = *reinterpret_cast<const ulonglong2*>(trp[r] + noff);
            }
            ulonglong2 v0 = *reinterpret_cast<const ulonglong2*>(svp0 + off);
            ulonglong2 v1 = *reinterpret_cast<const ulonglong2*>(svp1 + off);
            ulonglong2 v2 = *reinterpret_cast<const ulonglong2*>(svp2 + off);
            #pragma unroll
            for (int r = 0; r < RPW; r++) {
                acc[r][0] = ffma2(tv[r].x, v0.x, acc[r][0]);
                acc[r][0] = ffma2(tv[r].y, v0.y, acc[r][0]);
                acc[r][1] = ffma2(tv[r].x, v1.x, acc[r][1]);
                acc[r][1] = ffma2(tv[r].y, v1.y, acc[r][1]);
                acc[r][2] = ffma2(tv[r].x, v2.x, acc[r][2]);
                acc[r][2] = ffma2(tv[r].y, v2.y, acc[r][2]);
                nrm[r]    = ffma2(tv[r].x, tv[r].x, nrm[r]);
                nrm[r]    = ffma2(tv[r].y, tv[r].y, nrm[r]);
            }
            if (s < 15) {
                #pragma unroll
                for (int r = 0; r < RPW; r++) tv[r] = tnx[r];
            }
        }

        // ---- prime item k+1 text pointers + step-0 loads (tv is dead now);
        //      their latency hides under the tail's shuffle chains ----
        if (nvalid) {
            const int nb2   = next / chunks;
            const int nchk  = next % chunks;
            const float* ntb  = text + (size_t)nb2 * (size_t)T * D;
            const int    nbas = nchk * ROWS_CTA;
            #pragma unroll
            for (int r = 0; r < RPW; r++) {
                int tt = nbas + warp * RPW + r; if (tt > T - 1) tt = T - 1;
                trp[r] = ntb + (size_t)tt * D;
            }
            #pragma unroll
            for (int r = 0; r < RPW; r++)
                tv[r] = *reinterpret_cast<const ulonglong2*>(trp[r] + dl * 4);
        }

        // ---- reduction tail ----
        float wcmin = 1e30f, wcmax = -1e30f;
        #pragma unroll
        for (int r = 0; r < RPW; r++) {
            float d0 = hsum2(acc[r][0]);
            float d1 = hsum2(acc[r][1]);
            float d2 = hsum2(acc[r][2]);
            float ns = hsum2(nrm[r]);
            #pragma unroll
            for (int o = 1; o <= 4; o <<= 1) {
                d0 += __shfl_xor_sync(0xffffffffu, d0, o);
                d1 += __shfl_xor_sync(0xffffffffu, d1, o);
                d2 += __shfl_xor_sync(0xffffffffu, d2, o);
                ns += __shfl_xor_sync(0xffffffffu, ns, o);
            }
            float rin = rsqrtf(ns);
            float c0 = d0 * rin * vinv0;
            float c1 = d1 * rin * vinv1;
            float c2 = d2 * rin * vinv2;
            float cmn = fminf(c0, fminf(c1, c2));
            float cmx = fmaxf(c0, fmaxf(c1, c2));
            cmn = fminf(cmn, __shfl_xor_sync(0xffffffffu, cmn, 8));
            cmn = fminf(cmn, __shfl_xor_sync(0xffffffffu, cmn, 16));
            cmx = fmaxf(cmx, __shfl_xor_sync(0xffffffffu, cmx, 8));
            cmx = fmaxf(cmx, __shfl_xor_sync(0xffffffffu, cmx, 16));
            wcmin = fminf(wcmin, cmn);
            wcmax = fmaxf(wcmax, cmx);
        }

        if (lane == 0) { s_wmin[warp] = wcmin; s_wmax[warp] = wcmax; }
        __syncthreads();
        if (tid == 0) {
            float mn = s_wmin[0], mx = s_wmax[0];
            #pragma unroll
            for (int w = 1; w < 8; w++) {
                mn = fminf(mn, s_wmin[w]);
                mx = fmaxf(mx, s_wmax[w]);
            }
            g_part_min[item] = mn;
            g_part_max[item] = mx;
        }

        item  = next;
        valid = nvalid;
        cur  ^= 1;
    }

    // ================= grid barrier (all CTAs resident) =================
    if (tid == 0) {
        __threadfence();                       // publish partials (once per CTA)
        atomicAdd(&g_arrive, 1u);
        while (atomicAdd(&g_arrive, 0u) < (unsigned int)gridDim.x)
            __nanosleep(64);
    }
    __syncthreads();

    // ================= Phase 2: reduce + fill =================
    {
        float cmn = 1e30f, cmx = -1e30f;
        for (int j = tid; j < n_items; j += THREADS) {
            cmn = fminf(cmn, g_part_min[j]);
            cmx = fmaxf(cmx, g_part_max[j]);
        }
        red_mn[tid] = cmn; red_mx[tid] = cmx;
        __syncthreads();
        #pragma unroll
        for (int o = THREADS / 2; o > 0; o >>= 1) {
            if (tid < o) {
                red_mn[tid] = fminf(red_mn[tid], red_mn[tid + o]);
                red_mx[tid] = fmaxf(red_mx[tid], red_mx[tid + o]);
            }
            __syncthreads();
        }
        const float mn  = 1.0f - red_mx[0];     // global min of dis
        const float mx  = 1.0f - red_mn[0];     // global max of dis
        const float inv = 1.0f / (mx - mn);

        for (int i = blockIdx.x; i < B; i += gridDim.x) {
            float m0 = 1e30f, m1 = -1e30f;
            for (int c = 0; c < chunks; c++) {
                m0 = fminf(m0, g_part_min[i * chunks + c]);
                m1 = fmaxf(m1, g_part_max[i * chunks + c]);
            }
            const float rv = ((1.0f - m0) - mn) * inv;   // off-diagonal (dmax_i)
            const float dv = ((1.0f - m1) - mn) * inv;   // diagonal (dmin_i)
            float4* orow = reinterpret_cast<float4*>(out + (size_t)i * B);
            const int n4 = B >> 2;
            for (int c = tid; c < n4; c += THREADS) {
                float4 v = make_float4(rv, rv, rv, rv);
                if (c == (i >> 2)) reinterpret_cast<float*>(&v)[i & 3] = dv;
                orow[c] = v;
            }
        }
    }

    // ---- reset counters for the next graph replay ----
    __syncthreads();
    if (tid == 0) {
        unsigned int v = atomicAdd(&g_exit, 1u);
        if (v == gridDim.x - 1) {
            g_ticket = 0;
            g_arrive = 0;
            g_exit   = 0;
            __threadfence();
        }
    }
}

// ---------------------------------------------------------------------------
extern "C" void kernel_launch(void* const* d_in, const int* in_sizes, int n_in,
                              void* d_out, int out_size)
{
    const float* text  = (const float*)d_in[0];   // [B, T, D] fp32
    const float* video = (const float*)d_in[1];   // [B, F, D] fp32
    float* out = (float*)d_out;                   // [B, B] fp32

    const int B = in_sizes[1] / (FV * D);
    const int T = in_sizes[0] / (B * D);
    const int chunks = (T + ROWS_CTA - 1) / ROWS_CTA;   // 2 for T=77

    distance_persistent_kernel<<<GRID, THREADS>>>(text, video, out, T, B, chunks);
}

// round 11
// speedup vs baseline: 1.0617x; 1.0617x over previous
#include <cuda_runtime.h>
#include <cstdint>
#include <cstddef>

#define DEV_INLINE __device__ __forceinline__

constexpr int D        = 512;       // feature dim
constexpr int FV       = 12;        // video frames
constexpr int THREADS  = 256;       // 8 warps
constexpr int RPW      = 5;         // text rows per warp (single pass)
constexpr int ROWS_CTA = 8 * RPW;   // 40 rows per item
constexpr int GRID     = 296;       // 2 CTAs x 148 SMs, all co-resident

// scratch (allocation-free: __device__ globals)
__device__ float g_part_min[4096];
__device__ float g_part_max[4096];
__device__ unsigned int g_ticket = 0;
__device__ unsigned int g_arrive = 0;
__device__ unsigned int g_exit   = 0;

DEV_INLINE unsigned long long ffma2(unsigned long long a, unsigned long long b,
                                    unsigned long long c) {
    unsigned long long d;
    asm("fma.rn.f32x2 %0, %1, %2, %3;" : "=l"(d) : "l"(a), "l"(b), "l"(c));
    return d;
}

DEV_INLINE float hsum2(unsigned long long v) {
    float lo, hi;
    asm("mov.b64 {%0, %1}, %2;" : "=f"(lo), "=f"(hi) : "l"(v));
    return lo + hi;
}

DEV_INLINE void cp_async16(uint32_t smem_addr, const void* gptr) {
    asm volatile("cp.async.cg.shared.global [%0], [%1], 16;"
                 :: "r"(smem_addr), "l"(gptr));
}
#define CP_COMMIT()  asm volatile("cp.async.commit_group;")
#define CP_WAIT0()   asm volatile("cp.async.wait_group 0;" ::: "memory")

// ---------------------------------------------------------------------------
// Single persistent kernel, cross-item pipeline (register-clean version).
// Iteration k:
//   ticket k+1 -> wait video(k) -> issue video(k+1) into other buffer
//   -> compute item-k text ptrs + prime step-0 text LDGs   (hidden by norms)
//   -> norms(k) -> mainloop(k) -> tail(k) -> store partials.
// NOTHING beyond acc/nrm is live across the tail -> no spills (R10's bug).
// Phase 2: grid spin-barrier (all 296 CTAs resident by construction),
// float4+shuffle reduce of partials, cooperative output fill.
// Counters reset by last CTA; min/max is order-independent -> deterministic.
// ---------------------------------------------------------------------------
__global__ void __launch_bounds__(THREADS, 2)
distance_persistent_kernel(const float* __restrict__ text,
                           const float* __restrict__ video,
                           float* __restrict__ out,
                           int T, int B, int chunks)
{
    __shared__ float sv[2][FV * D];       // 2 x 24 KB video tiles
    __shared__ float s_vinv[FV];
    __shared__ float s_wmin[8], s_wmax[8];
    __shared__ float s_red[16];
    __shared__ unsigned int s_item, s_next;

    const int tid  = threadIdx.x;
    const int warp = tid >> 5;
    const int lane = tid & 31;
    const int fg   = lane >> 3;    // 0..3 : which group of 3 video rows
    const int dl   = lane & 7;     // 0..7 : which slice of D
    const int n_items = B * chunks;

    // ---------------- prologue: first ticket + first video staging ----------------
    if (tid == 0) s_item = atomicAdd(&g_ticket, 1u);
    __syncthreads();
    unsigned int item = s_item;
    bool valid = item < (unsigned int)n_items;
    int cur = 0;

    if (valid) {
        const int b = item / chunks;
        const char* vsrc = reinterpret_cast<const char*>(video + (size_t)b * FV * D);
        uint32_t svb = (uint32_t)__cvta_generic_to_shared(&sv[0][0]);
        #pragma unroll
        for (int i = tid; i < FV * (D / 4); i += THREADS)
            cp_async16(svb + i * 16, vsrc + i * 16);
        CP_COMMIT();
    }

    // ---------------- item loop ----------------
    while (valid) {
        if (tid == 0) s_next = atomicAdd(&g_ticket, 1u);
        CP_WAIT0();                       // video(item) resident
        __syncthreads();                  // broadcast s_next; all past prev phase
        const unsigned int next = s_next;
        const bool nvalid = next < (unsigned int)n_items;

        // ---- issue video staging for item k+1 (overlaps all of compute(k)) ----
        if (nvalid) {
            const int nb = next / chunks;
            const char* nvsrc = reinterpret_cast<const char*>(video + (size_t)nb * FV * D);
            uint32_t svb = (uint32_t)__cvta_generic_to_shared(&sv[cur ^ 1][0]);
            #pragma unroll
            for (int i = tid; i < FV * (D / 4); i += THREADS)
                cp_async16(svb + i * 16, nvsrc + i * 16);
            CP_COMMIT();
        }

        // ---- item-k text row pointers + step-0 prime (hidden behind norms) ----
        const int b     = item / chunks;
        const int chunk = item % chunks;
        const float* tb = text + (size_t)b * (size_t)T * D;
        const int base  = chunk * ROWS_CTA;
        const float* trp[RPW];
        #pragma unroll
        for (int r = 0; r < RPW; r++) {
            int tt = base + warp * RPW + r; if (tt > T - 1) tt = T - 1;
            trp[r] = tb + (size_t)tt * D;
        }
        ulonglong2 tv[RPW];
        #pragma unroll
        for (int r = 0; r < RPW; r++)
            tv[r] = *reinterpret_cast<const ulonglong2*>(trp[r] + dl * 4);

        // ---- inverse norms of the 12 video rows (from sv[cur]) ----
        const float* svc = &sv[cur][0];
        for (int f = warp; f < FV; f += 8) {
            float s = 0.f;
            #pragma unroll
            for (int c = lane; c < D / 4; c += 32) {
                float4 x = *reinterpret_cast<const float4*>(&svc[f * D + c * 4]);
                s += x.x * x.x + x.y * x.y + x.z * x.z + x.w * x.w;
            }
            #pragma unroll
            for (int o = 16; o > 0; o >>= 1) s += __shfl_xor_sync(0xffffffffu, s, o);
            if (lane == 0) s_vinv[f] = rsqrtf(s);
        }
        __syncthreads();

        const int f0 = fg * 3;
        const float vinv0 = s_vinv[f0 + 0];
        const float vinv1 = s_vinv[f0 + 1];
        const float vinv2 = s_vinv[f0 + 2];
        const float* svp0 = &svc[(f0 + 0) * D];
        const float* svp1 = &svc[(f0 + 1) * D];
        const float* svp2 = &svc[(f0 + 2) * D];

        unsigned long long acc[RPW][3];
        unsigned long long nrm[RPW];
        #pragma unroll
        for (int r = 0; r < RPW; r++) {
            acc[r][0] = 0ull; acc[r][1] = 0ull; acc[r][2] = 0ull; nrm[r] = 0ull;
        }

        // ---- mainloop: video from shared, text from global (1-step prefetch) ----
        #pragma unroll
        for (int s = 0; s < 16; s++) {
            const int off = (dl + 8 * s) * 4;
            ulonglong2 tnx[RPW];
            if (s < 15) {
                const int noff = (dl + 8 * (s + 1)) * 4;
                #pragma unroll
                for (int r = 0; r < RPW; r++)
                    tnx[r] = *reinterpret_cast<const ulonglong2*>(trp[r] + noff);
            }
            ulonglong2 v0 = *reinterpret_cast<const ulonglong2*>(svp0 + off);
            ulonglong2 v1 = *reinterpret_cast<const ulonglong2*>(svp1 + off);
            ulonglong2 v2 = *reinterpret_cast<const ulonglong2*>(svp2 + off);
            #pragma unroll
            for (int r = 0; r < RPW; r++) {
                acc[r][0] = ffma2(tv[r].x, v0.x, acc[r][0]);
                acc[r][0] = ffma2(tv[r].y, v0.y, acc[r][0]);
                acc[r][1] = ffma2(tv[r].x, v1.x, acc[r][1]);
                acc[r][1] = ffma2(tv[r].y, v1.y, acc[r][1]);
                acc[r][2] = ffma2(tv[r].x, v2.x, acc[r][2]);
                acc[r][2] = ffma2(tv[r].y, v2.y, acc[r][2]);
                nrm[r]    = ffma2(tv[r].x, tv[r].x, nrm[r]);
                nrm[r]    = ffma2(tv[r].y, tv[r].y, nrm[r]);
            }
            if (s < 15) {
                #pragma unroll
                for (int r = 0; r < RPW; r++) tv[r] = tnx[r];
            }
        }

        // ---- reduction tail (only acc/nrm live here) ----
        float wcmin = 1e30f, wcmax = -1e30f;
        #pragma unroll
        for (int r = 0; r < RPW; r++) {
            float d0 = hsum2(acc[r][0]);
            float d1 = hsum2(acc[r][1]);
            float d2 = hsum2(acc[r][2]);
            float ns = hsum2(nrm[r]);
            #pragma unroll
            for (int o = 1; o <= 4; o <<= 1) {
                d0 += __shfl_xor_sync(0xffffffffu, d0, o);
                d1 += __shfl_xor_sync(0xffffffffu, d1, o);
                d2 += __shfl_xor_sync(0xffffffffu, d2, o);
                ns += __shfl_xor_sync(0xffffffffu, ns, o);
            }
            float rin = rsqrtf(ns);
            float c0 = d0 * rin * vinv0;
            float c1 = d1 * rin * vinv1;
            float c2 = d2 * rin * vinv2;
            float cmn = fminf(c0, fminf(c1, c2));
            float cmx = fmaxf(c0, fmaxf(c1, c2));
            cmn = fminf(cmn, __shfl_xor_sync(0xffffffffu, cmn, 8));
            cmn = fminf(cmn, __shfl_xor_sync(0xffffffffu, cmn, 16));
            cmx = fmaxf(cmx, __shfl_xor_sync(0xffffffffu, cmx, 8));
            cmx = fmaxf(cmx, __shfl_xor_sync(0xffffffffu, cmx, 16));
            wcmin = fminf(wcmin, cmn);
            wcmax = fmaxf(wcmax, cmx);
        }

        if (lane == 0) { s_wmin[warp] = wcmin; s_wmax[warp] = wcmax; }
        __syncthreads();
        if (tid == 0) {
            float mn = s_wmin[0], mx = s_wmax[0];
            #pragma unroll
            for (int w = 1; w < 8; w++) {
                mn = fminf(mn, s_wmin[w]);
                mx = fmaxf(mx, s_wmax[w]);
            }
            g_part_min[item] = mn;
            g_part_max[item] = mx;
        }

        item  = next;
        valid = nvalid;
        cur  ^= 1;
    }

    // ================= grid barrier (all CTAs resident) =================
    if (tid == 0) {
        __threadfence();                       // publish partials (once per CTA)
        atomicAdd(&g_arrive, 1u);
        while (atomicAdd(&g_arrive, 0u) < (unsigned int)gridDim.x)
            __nanosleep(64);
    }
    __syncthreads();

    // ================= Phase 2: reduce (float4 + shuffles) + fill =================
    {
        float cmn = 1e30f, cmx = -1e30f;
        for (int j = tid * 4; j < n_items; j += THREADS * 4) {
            float4 a = *reinterpret_cast<const float4*>(&g_part_min[j]);
            float4 e = *reinterpret_cast<const float4*>(&g_part_max[j]);
            cmn = fminf(cmn, fminf(fminf(a.x, a.y), fminf(a.z, a.w)));
            cmx = fmaxf(cmx, fmaxf(fmaxf(e.x, e.y), fmaxf(e.z, e.w)));
        }
        #pragma unroll
        for (int o = 16; o > 0; o >>= 1) {
            cmn = fminf(cmn, __shfl_xor_sync(0xffffffffu, cmn, o));
            cmx = fmaxf(cmx, __shfl_xor_sync(0xffffffffu, cmx, o));
        }
        if (lane == 0) { s_red[warp] = cmn; s_red[8 + warp] = cmx; }
        __syncthreads();
        float rmn = s_red[0], rmx = s_red[8];
        #pragma unroll
        for (int w = 1; w < 8; w++) {
            rmn = fminf(rmn, s_red[w]);
            rmx = fmaxf(rmx, s_red[8 + w]);
        }
        const float mn  = 1.0f - rmx;           // global min of dis
        const float mx  = 1.0f - rmn;           // global max of dis
        const float inv = 1.0f / (mx - mn);

        for (int i = blockIdx.x; i < B; i += gridDim.x) {
            float m0 = 1e30f, m1 = -1e30f;
            for (int c = 0; c < chunks; c++) {
                m0 = fminf(m0, g_part_min[i * chunks + c]);
                m1 = fmaxf(m1, g_part_max[i * chunks + c]);
            }
            const float rv = ((1.0f - m0) - mn) * inv;   // off-diagonal (dmax_i)
            const float dv = ((1.0f - m1) - mn) * inv;   // diagonal (dmin_i)
            float4* orow = reinterpret_cast<float4*>(out + (size_t)i * B);
            const int n4 = B >> 2;
            for (int c = tid; c < n4; c += THREADS) {
                float4 v = make_float4(rv, rv, rv, rv);
                if (c == (i >> 2)) reinterpret_cast<float*>(&v)[i & 3] = dv;
                orow[c] = v;
            }
        }
    }

    // ---- reset counters for the next graph replay ----
    __syncthreads();
    if (tid == 0) {
        unsigned int v = atomicAdd(&g_exit, 1u);
        if (v == gridDim.x - 1) {
            g_ticket = 0;
            g_arrive = 0;
            g_exit   = 0;
            __threadfence();
        }
    }
}

// ---------------------------------------------------------------------------
extern "C" void kernel_launch(void* const* d_in, const int* in_sizes, int n_in,
                              void* d_out, int out_size)
{
    const float* text  = (const float*)d_in[0];   // [B, T, D] fp32
    const float* video = (const float*)d_in[1];   // [B, F, D] fp32
    float* out = (float*)d_out;                   // [B, B] fp32

    const int B = in_sizes[1] / (FV * D);
    const int T = in_sizes[0] / (B * D);
    const int chunks = (T + ROWS_CTA - 1) / ROWS_CTA;   // 2 for T=77

    distance_persistent_kernel<<<GRID, THREADS>>>(text, video, out, T, B, chunks);
}